// round 6
// baseline (speedup 1.0000x reference)
#include <cuda_runtime.h>
#include <cuda_bf16.h>
#include <cstdint>

// Problem constants (fixed shapes from reference)
#define CB 4
#define CT 8192
#define CD 1024
#define CH 1024
#define CO 1024
#define CM (CB*CT)    // 32768 rows
#define NCHUNK 64
#define CHUNK (CT/NCHUNK)   // 128
#define LN_EPS 1e-5f
#define QMAX 16000.0f

// ---------------- scratch (device globals; no allocation allowed) -------------
__device__ int8_t g_xhi[(size_t)CM*CD], g_xlo[(size_t)CM*CD];
__device__ int8_t g_w1hi[(size_t)CH*CD], g_w1lo[(size_t)CH*CD];
__device__ int8_t g_w2hi[(size_t)CH*CD], g_w2lo[(size_t)CH*CD];
__device__ int8_t g_w3hi[(size_t)CO*CH], g_w3lo[(size_t)CO*CH];
__device__ int8_t g_hnhi[(size_t)CM*CH], g_hnlo[(size_t)CM*CH];
__device__ float g_sx[CM], g_sw1[CH], g_sw2[CH], g_sw3[CO], g_shn[CM];
__device__ float g_ih[(size_t)CM*CH];
__device__ float g_gate[(size_t)CM*CH];
__device__ float g_cA[CB*NCHUNK*CH];
__device__ float g_cB[CB*NCHUNK*CH];
__device__ float g_pref[CB*NCHUNK*CH];

// ------------------------------ helpers ---------------------------------------
__device__ __forceinline__ uint32_t s2u(const void* p) {
    return (uint32_t)__cvta_generic_to_shared(p);
}
__device__ __forceinline__ void cp16(uint32_t s, const void* g) {
    asm volatile("cp.async.cg.shared.global [%0], [%1], 16;" :: "r"(s), "l"(g));
}
#define CP_COMMIT() asm volatile("cp.async.commit_group;" ::: "memory")

__device__ __forceinline__ void ldsm4(uint32_t* r, uint32_t addr) {
    asm volatile("ldmatrix.sync.aligned.m8n8.x4.shared.b16 {%0,%1,%2,%3}, [%4];"
        : "=r"(r[0]), "=r"(r[1]), "=r"(r[2]), "=r"(r[3]) : "r"(addr));
}

#define MMA_S8(d, a, b) \
    asm volatile("mma.sync.aligned.m16n8k32.row.col.s32.s8.s8.s32 " \
        "{%0,%1,%2,%3}, {%4,%5,%6,%7}, {%8,%9}, {%0,%1,%2,%3};" \
        : "+r"(d[0]), "+r"(d[1]), "+r"(d[2]), "+r"(d[3]) \
        : "r"(a[0]), "r"(a[1]), "r"(a[2]), "r"(a[3]), "r"(b[0]), "r"(b[1]))

// --------------------- per-row 15-bit quantization ----------------------------
// v ~= s * (128*hi + lo), s = rowmax/QMAX. One block per row of 1024 floats.
__global__ __launch_bounds__(256) void quant_rows(
    const float* __restrict__ src, int8_t* __restrict__ hi,
    int8_t* __restrict__ lo, float* __restrict__ scale)
{
    __shared__ float sred[8];
    const size_t base = (size_t)blockIdx.x * 1024;
    const int h = threadIdx.x * 4;
    float4 v = *reinterpret_cast<const float4*>(src + base + h);
    float vv[4] = {v.x, v.y, v.z, v.w};
    float m = fmaxf(fmaxf(fabsf(vv[0]), fabsf(vv[1])),
                    fmaxf(fabsf(vv[2]), fabsf(vv[3])));
#pragma unroll
    for (int off = 16; off > 0; off >>= 1)
        m = fmaxf(m, __shfl_xor_sync(0xffffffffu, m, off));
    const int warp = threadIdx.x >> 5, lane = threadIdx.x & 31;
    if (lane == 0) sred[warp] = m;
    __syncthreads();
    if (threadIdx.x < 32) {
        float a = (lane < 8) ? sred[lane] : 0.f;
#pragma unroll
        for (int off = 4; off > 0; off >>= 1)
            a = fmaxf(a, __shfl_xor_sync(0xffffffffu, a, off));
        if (lane == 0) sred[0] = a;
    }
    __syncthreads();
    const float rmax = sred[0];
    const float rs = (rmax > 1e-30f) ? (QMAX / rmax) : 0.f;
    if (threadIdx.x == 0) scale[blockIdx.x] = rmax * (1.f / QMAX);

    char hb[4], lb[4];
#pragma unroll
    for (int c = 0; c < 4; c++) {
        int q = __float2int_rn(vv[c] * rs);
        int qh = (q + 64) >> 7;
        hb[c] = (char)qh;
        lb[c] = (char)(q - (qh << 7));
    }
    *reinterpret_cast<char4*>(hi + base + h) = make_char4(hb[0], hb[1], hb[2], hb[3]);
    *reinterpret_cast<char4*>(lo + base + h) = make_char4(lb[0], lb[1], lb[2], lb[3]);
}

// ---------------------- int8 split tensor-core GEMM ---------------------------
// C[m][n] = sa[m]*sb[n]*(16384*HH + 128*CR) (+bias[n])
// HH = Ahi.Bhi, CR = Ahi.Blo + Alo.Bhi (lo.lo dropped: ~2^-14 of cross term).
// Dual-output: gridDim.x=16 -> bx<8 set1, else set2. 128x128 tile, BK=128 bytes,
// 3-stage cp.async, ldmatrix.x4 (byte layout identical to bf16 k16), XOR swizzle.

#define PART_B 16384               // 128 rows x 128B
#define STAGE_B (4*PART_B)         // Ahi|Alo|Bhi|Blo = 64KB per stage
#define NSTAGE 3
#define DYN_B (NSTAGE*STAGE_B + 1024)

__global__ __launch_bounds__(256, 1) void gemm_s8x2(
    const int8_t* __restrict__ Ahi, const int8_t* __restrict__ Alo,
    const float* __restrict__ sa,
    const int8_t* __restrict__ B1hi, const int8_t* __restrict__ B1lo,
    const float* __restrict__ sb1,
    const int8_t* __restrict__ B2hi, const int8_t* __restrict__ B2lo,
    const float* __restrict__ sb2,
    const float* __restrict__ bias1, const float* __restrict__ bias2,
    float* __restrict__ C1, float* __restrict__ C2,
    int M, int N, int K)   // K in bytes (=elements)
{
    extern __shared__ char dyn[];
    const uint32_t tile = (s2u(dyn) + 127u) & ~127u;

    const int tid = threadIdx.x;
    const int bx = blockIdx.x;
    const bool first = bx < 8;
    const int8_t* Bhi = first ? B1hi : B2hi;
    const int8_t* Blo = first ? B1lo : B2lo;
    const float* sb = first ? sb1 : sb2;
    const float* bias = first ? bias1 : bias2;
    float* C = first ? C1 : C2;
    const int m0 = blockIdx.y * 128;
    const int n0 = (bx & 7) * 128;

    const int wid = tid >> 5, lane = tid & 31;
    const int wm = wid >> 2;       // 0..1
    const int wn = wid & 3;        // 0..3

    const int8_t* srcs[4] = {
        Ahi + (size_t)m0 * K, Alo + (size_t)m0 * K,
        Bhi + (size_t)n0 * K, Blo + (size_t)n0 * K };

    // cp.async: thread t -> row r = t>>1, 16B chunks (t&1)*4 .. +3
    const int lr = tid >> 1;
    const int lc0 = (tid & 1) * 4;
    const int lsw = lr & 7;

    auto issue = [&](int s) {
        uint32_t sb_ = tile + (uint32_t)(s % NSTAGE) * STAGE_B;
        int k0 = s * 128;
#pragma unroll
        for (int p = 0; p < 4; p++) {
            const int8_t* g = srcs[p] + (size_t)lr * K + k0 + lc0 * 16;
            uint32_t base = sb_ + p * PART_B + lr * 128;
#pragma unroll
            for (int c = 0; c < 4; c++)
                cp16(base + (((lc0 + c) ^ lsw) << 4), g + c * 16);
        }
        CP_COMMIT();
    };

    // ldmatrix address precomputation (byte layout same as bf16 variant)
    const int arow = wm * 64 + (lane & 15);
    const int ahalf = lane >> 4;
    const int asw = arow & 7;
    const int brow = wn * 32 + ((lane >> 4) << 3) + (lane & 7);
    const int bhalf = (lane >> 3) & 1;
    const int bsw = brow & 7;

    int acc_hh[4][4][4], acc_cr[4][4][4];
#pragma unroll
    for (int i = 0; i < 4; i++)
#pragma unroll
        for (int j = 0; j < 4; j++)
#pragma unroll
            for (int c = 0; c < 4; c++) { acc_hh[i][j][c] = 0; acc_cr[i][j][c] = 0; }

    issue(0); issue(1);

    const int NIT = K / 128;   // 8
    for (int it = 0; it < NIT; ++it) {
        if (it + 1 < NIT) asm volatile("cp.async.wait_group 1;" ::: "memory");
        else              asm volatile("cp.async.wait_group 0;" ::: "memory");
        __syncthreads();
        if (it + 2 < NIT) issue(it + 2);

        uint32_t sb_ = tile + (uint32_t)(it % NSTAGE) * STAGE_B;
        uint32_t aAhi = sb_              + arow * 128;
        uint32_t aAlo = sb_ +     PART_B + arow * 128;
        uint32_t aBhi = sb_ + 2 * PART_B + brow * 128;
        uint32_t aBlo = sb_ + 3 * PART_B + brow * 128;

#pragma unroll
        for (int ks = 0; ks < 4; ks++) {   // each ks = 32 k-bytes = 2 chunks
            const int ac = (2 * ks + ahalf) ^ asw;
            const int bc = (2 * ks + bhalf) ^ bsw;
            uint32_t ahi[4][4], alo[4][4], bhi[4][2], blo[4][2];
#pragma unroll
            for (int i = 0; i < 4; i++) {
                ldsm4(ahi[i], aAhi + i * (16 * 128) + (ac << 4));
                ldsm4(alo[i], aAlo + i * (16 * 128) + (ac << 4));
            }
#pragma unroll
            for (int q = 0; q < 2; q++) {
                uint32_t rb[4];
                ldsm4(rb, aBhi + q * (16 * 128) + (bc << 4));
                bhi[q*2+0][0] = rb[0]; bhi[q*2+0][1] = rb[1];
                bhi[q*2+1][0] = rb[2]; bhi[q*2+1][1] = rb[3];
                ldsm4(rb, aBlo + q * (16 * 128) + (bc << 4));
                blo[q*2+0][0] = rb[0]; blo[q*2+0][1] = rb[1];
                blo[q*2+1][0] = rb[2]; blo[q*2+1][1] = rb[3];
            }
#pragma unroll
            for (int i = 0; i < 4; i++)
#pragma unroll
                for (int j = 0; j < 4; j++) {
                    MMA_S8(acc_hh[i][j], ahi[i], bhi[j]);
                    MMA_S8(acc_cr[i][j], ahi[i], blo[j]);
                    MMA_S8(acc_cr[i][j], alo[i], bhi[j]);
                }
        }
    }

    // epilogue: dequantize
    const int g = lane >> 2, tq = lane & 3;
#pragma unroll
    for (int i = 0; i < 4; i++) {
        const int m = m0 + wm * 64 + i * 16 + g;
        const float sa0 = sa[m], sa8 = sa[m + 8];
#pragma unroll
        for (int j = 0; j < 4; j++) {
            const int n = n0 + wn * 32 + j * 8 + tq * 2;
            const float sbn0 = sb[n], sbn1 = sb[n + 1];
            float b0 = 0.f, b1 = 0.f;
            if (bias) { b0 = bias[n]; b1 = bias[n + 1]; }
            float2 v0, v1;
            v0.x = sa0 * sbn0 * (16384.f * (float)acc_hh[i][j][0] + 128.f * (float)acc_cr[i][j][0]) + b0;
            v0.y = sa0 * sbn1 * (16384.f * (float)acc_hh[i][j][1] + 128.f * (float)acc_cr[i][j][1]) + b1;
            v1.x = sa8 * sbn0 * (16384.f * (float)acc_hh[i][j][2] + 128.f * (float)acc_cr[i][j][2]) + b0;
            v1.y = sa8 * sbn1 * (16384.f * (float)acc_hh[i][j][3] + 128.f * (float)acc_cr[i][j][3]) + b1;
            *reinterpret_cast<float2*>(C + (size_t)m * N + n)       = v0;
            *reinterpret_cast<float2*>(C + (size_t)(m + 8) * N + n) = v1;
        }
    }
}

// ---- pass A (fused): gate/alpha/beta from raw GEMM outputs + local scan ------
__global__ __launch_bounds__(256) void scan_local(
    float* __restrict__ ih_arr, float* __restrict__ gate_arr,
    const float* __restrict__ b_ih, const float* __restrict__ b_g,
    const float* __restrict__ log_a,
    float* __restrict__ cA, float* __restrict__ cB)
{
    int idx = blockIdx.x * blockDim.x + threadIdx.x;  // B*H*NCHUNK threads
    int h = idx % CH;
    int c = (idx / CH) % NCHUNK;
    int b = idx / (CH * NCHUNK);
    const float bg = b_g[h], bi = b_ih[h], ea = __expf(log_a[h]);
    size_t base = ((size_t)b * CT + (size_t)c * CHUNK) * CH + h;
    float p = 1.f, hl = 0.f;
#pragma unroll 8
    for (int t = 0; t < CHUNK; t++) {
        size_t o = base + (size_t)t * CH;
        float graw = gate_arr[o];
        float iraw = ih_arr[o];
        float gate = 1.f / (1.f + __expf(-(graw + bg)));
        float beta = gate * (iraw + bi);
        float a = (1.f - gate) * ea;
        hl = fmaf(a, hl, beta);
        p *= a;
        gate_arr[o] = p;
        ih_arr[o] = hl;
    }
    cA[((size_t)b * NCHUNK + c) * CH + h] = p;
    cB[((size_t)b * NCHUNK + c) * CH + h] = hl;
}

// ---------------- pass B: scan across chunk summaries per (b,h) ---------------
__global__ __launch_bounds__(256) void scan_carry(
    const float* __restrict__ cA, const float* __restrict__ cB,
    float* __restrict__ pref)
{
    int idx = blockIdx.x * blockDim.x + threadIdx.x;  // B*H threads
    int h = idx % CH;
    int b = idx / CH;
    float run = 0.f;
#pragma unroll
    for (int c = 0; c < NCHUNK; c++) {
        size_t o = ((size_t)b * NCHUNK + c) * CH + h;
        pref[o] = run;
        run = fmaf(cA[o], run, cB[o]);
    }
}

// -- pass C: fixup h = h_local + P*carry, fused LayerNorm -> int8 hi/lo + scale -
__global__ __launch_bounds__(256) void fix_ln(
    const float* __restrict__ P, const float* __restrict__ HL,
    const float* __restrict__ pref,
    const float* __restrict__ lng, const float* __restrict__ lnb,
    int8_t* __restrict__ hnhi, int8_t* __restrict__ hnlo,
    float* __restrict__ shn)
{
    __shared__ float sred[16];
    const int row = blockIdx.x;
    const int b = row / CT;
    const int t = row % CT;
    const int c = t / CHUNK;
    const size_t base = (size_t)row * CH;
    const float* prow = pref + ((size_t)b * NCHUNK + c) * CH;
    const int h = threadIdx.x * 4;
    const int warp = threadIdx.x >> 5, lane = threadIdx.x & 31;

    float4 p4  = *reinterpret_cast<const float4*>(P + base + h);
    float4 hl4 = *reinterpret_cast<const float4*>(HL + base + h);
    float4 pr4 = *reinterpret_cast<const float4*>(prow + h);
    float v[4];
    v[0] = fmaf(p4.x, pr4.x, hl4.x);
    v[1] = fmaf(p4.y, pr4.y, hl4.y);
    v[2] = fmaf(p4.z, pr4.z, hl4.z);
    v[3] = fmaf(p4.w, pr4.w, hl4.w);

    float s = v[0] + v[1] + v[2] + v[3];
    float ss = v[0]*v[0] + v[1]*v[1] + v[2]*v[2] + v[3]*v[3];
#pragma unroll
    for (int off = 16; off > 0; off >>= 1) {
        s  += __shfl_xor_sync(0xffffffffu, s,  off);
        ss += __shfl_xor_sync(0xffffffffu, ss, off);
    }
    if (lane == 0) { sred[warp] = s; sred[8 + warp] = ss; }
    __syncthreads();
    if (threadIdx.x < 32) {
        float a  = (lane < 8) ? sred[lane]     : 0.f;
        float b2 = (lane < 8) ? sred[8 + lane] : 0.f;
#pragma unroll
        for (int off = 4; off > 0; off >>= 1) {
            a  += __shfl_xor_sync(0xffffffffu, a,  off);
            b2 += __shfl_xor_sync(0xffffffffu, b2, off);
        }
        if (lane == 0) { sred[0] = a; sred[1] = b2; }
    }
    __syncthreads();
    const float mu  = sred[0] * (1.f / CH);
    const float var = sred[1] * (1.f / CH) - mu * mu;
    const float inv = rsqrtf(var + LN_EPS);

    float4 g4 = *reinterpret_cast<const float4*>(lng + h);
    float4 b4 = *reinterpret_cast<const float4*>(lnb + h);
    float o[4];
    o[0] = (v[0] - mu) * inv * g4.x + b4.x;
    o[1] = (v[1] - mu) * inv * g4.y + b4.y;
    o[2] = (v[2] - mu) * inv * g4.z + b4.z;
    o[3] = (v[3] - mu) * inv * g4.w + b4.w;

    // row-max reduction for quantization scale
    float m = fmaxf(fmaxf(fabsf(o[0]), fabsf(o[1])),
                    fmaxf(fabsf(o[2]), fabsf(o[3])));
#pragma unroll
    for (int off = 16; off > 0; off >>= 1)
        m = fmaxf(m, __shfl_xor_sync(0xffffffffu, m, off));
    if (lane == 0) sred[warp] = m;
    __syncthreads();
    if (threadIdx.x < 32) {
        float a = (lane < 8) ? sred[lane] : 0.f;
#pragma unroll
        for (int off = 4; off > 0; off >>= 1)
            a = fmaxf(a, __shfl_xor_sync(0xffffffffu, a, off));
        if (lane == 0) sred[0] = a;
    }
    __syncthreads();
    const float rmax = sred[0];
    const float rs = (rmax > 1e-30f) ? (QMAX / rmax) : 0.f;
    if (threadIdx.x == 0) shn[row] = rmax * (1.f / QMAX);

    char hb[4], lb[4];
#pragma unroll
    for (int k = 0; k < 4; k++) {
        int q = __float2int_rn(o[k] * rs);
        int qh = (q + 64) >> 7;
        hb[k] = (char)qh;
        lb[k] = (char)(q - (qh << 7));
    }
    *reinterpret_cast<char4*>(hnhi + base + h) = make_char4(hb[0], hb[1], hb[2], hb[3]);
    *reinterpret_cast<char4*>(hnlo + base + h) = make_char4(lb[0], lb[1], lb[2], lb[3]);
}

// --------------------------------- launcher ----------------------------------
extern "C" void kernel_launch(void* const* d_in, const int* in_sizes, int n_in,
                              void* d_out, int out_size)
{
    const float* x      = (const float*)d_in[0];
    const float* W_ih   = (const float*)d_in[1];
    const float* b_ih   = (const float*)d_in[2];
    const float* log_a  = (const float*)d_in[3];
    const float* W_gate = (const float*)d_in[4];
    const float* b_gate = (const float*)d_in[5];
    const float* W_out  = (const float*)d_in[6];
    const float* b_out  = (const float*)d_in[7];
    const float* ln_g   = (const float*)d_in[8];
    const float* ln_b   = (const float*)d_in[9];
    float* out = (float*)d_out;

    int8_t *xhi, *xlo, *w1hi, *w1lo, *w2hi, *w2lo, *w3hi, *w3lo, *hnhi, *hnlo;
    float *sx, *sw1, *sw2, *sw3, *shn;
    float *ih, *gt, *cA, *cB, *pref;
    cudaGetSymbolAddress((void**)&xhi,  g_xhi);
    cudaGetSymbolAddress((void**)&xlo,  g_xlo);
    cudaGetSymbolAddress((void**)&w1hi, g_w1hi);
    cudaGetSymbolAddress((void**)&w1lo, g_w1lo);
    cudaGetSymbolAddress((void**)&w2hi, g_w2hi);
    cudaGetSymbolAddress((void**)&w2lo, g_w2lo);
    cudaGetSymbolAddress((void**)&w3hi, g_w3hi);
    cudaGetSymbolAddress((void**)&w3lo, g_w3lo);
    cudaGetSymbolAddress((void**)&hnhi, g_hnhi);
    cudaGetSymbolAddress((void**)&hnlo, g_hnlo);
    cudaGetSymbolAddress((void**)&sx,   g_sx);
    cudaGetSymbolAddress((void**)&sw1,  g_sw1);
    cudaGetSymbolAddress((void**)&sw2,  g_sw2);
    cudaGetSymbolAddress((void**)&sw3,  g_sw3);
    cudaGetSymbolAddress((void**)&shn,  g_shn);
    cudaGetSymbolAddress((void**)&ih,   g_ih);
    cudaGetSymbolAddress((void**)&gt,   g_gate);
    cudaGetSymbolAddress((void**)&cA,   g_cA);
    cudaGetSymbolAddress((void**)&cB,   g_cB);
    cudaGetSymbolAddress((void**)&pref, g_pref);

    cudaFuncSetAttribute(gemm_s8x2,
                         cudaFuncAttributeMaxDynamicSharedMemorySize, DYN_B);

    // 15-bit row quantization
    quant_rows<<<CM, 256>>>(x,      xhi,  xlo,  sx);
    quant_rows<<<CH, 256>>>(W_ih,   w1hi, w1lo, sw1);
    quant_rows<<<CH, 256>>>(W_gate, w2hi, w2lo, sw2);
    quant_rows<<<CO, 256>>>(W_out,  w3hi, w3lo, sw3);

    // fused dual input GEMM: bx<8 -> (W_ih -> ih), bx>=8 -> (W_gate -> gt)
    gemm_s8x2<<<dim3(16, CM / 128), 256, DYN_B>>>(
        xhi, xlo, sx, w1hi, w1lo, sw1, w2hi, w2lo, sw2,
        nullptr, nullptr, ih, gt, CM, CH, CD);

    // fused elementwise + chunked scan
    scan_local<<<(CB * CH * NCHUNK) / 256, 256>>>(ih, gt, b_ih, b_gate, log_a, cA, cB);
    scan_carry<<<(CB * CH) / 256, 256>>>(cA, cB, pref);
    fix_ln<<<CM, 256>>>(gt, ih, pref, ln_g, ln_b, hnhi, hnlo, shn);

    // output GEMM (single-output: both sets identical, grid.x = 8)
    gemm_s8x2<<<dim3(8, CM / 128), 256, DYN_B>>>(
        hnhi, hnlo, shn, w3hi, w3lo, sw3, w3hi, w3lo, sw3,
        b_out, b_out, out, out, CM, CO, CH);
}

// round 7
// speedup vs baseline: 3.3280x; 3.3280x over previous
#include <cuda_runtime.h>
#include <cuda_bf16.h>
#include <cuda_fp16.h>
#include <cstdint>

// Problem constants (fixed shapes from reference)
#define CB 4
#define CT 8192
#define CD 1024
#define CH 1024
#define CO 1024
#define CM (CB*CT)    // 32768 rows
#define NCHUNK 64
#define CHUNK (CT/NCHUNK)   // 128
#define LN_EPS 1e-5f

// ---------------- scratch (device globals; no allocation allowed) -------------
__device__ __half g_xh[(size_t)CM*CD];
__device__ __half g_w1h[(size_t)CH*CD], g_w2h[(size_t)CH*CD];
__device__ __nv_bfloat16 g_w3hi[(size_t)CO*CH], g_w3lo[(size_t)CO*CH];
__device__ float g_ih[(size_t)CM*CH];
__device__ float g_gate[(size_t)CM*CH];
__device__ __nv_bfloat16 g_hnhi[(size_t)CM*CH];
__device__ __nv_bfloat16 g_hnlo[(size_t)CM*CH];
__device__ float g_cA[CB*NCHUNK*CH];
__device__ float g_cB[CB*NCHUNK*CH];
__device__ float g_pref[CB*NCHUNK*CH];

// ------------------------------ helpers ---------------------------------------
__device__ __forceinline__ uint32_t s2u(const void* p) {
    return (uint32_t)__cvta_generic_to_shared(p);
}
__device__ __forceinline__ void cp16(uint32_t s, const void* g) {
    asm volatile("cp.async.cg.shared.global [%0], [%1], 16;" :: "r"(s), "l"(g));
}
#define CP_COMMIT() asm volatile("cp.async.commit_group;" ::: "memory")

__device__ __forceinline__ void ldsm4(uint32_t* r, uint32_t addr) {
    asm volatile("ldmatrix.sync.aligned.m8n8.x4.shared.b16 {%0,%1,%2,%3}, [%4];"
        : "=r"(r[0]), "=r"(r[1]), "=r"(r[2]), "=r"(r[3]) : "r"(addr));
}

#define MMA_BF16(d, a, b) \
    asm volatile("mma.sync.aligned.m16n8k16.row.col.f32.bf16.bf16.f32 " \
        "{%0,%1,%2,%3}, {%4,%5,%6,%7}, {%8,%9}, {%0,%1,%2,%3};" \
        : "+f"(d[0]), "+f"(d[1]), "+f"(d[2]), "+f"(d[3]) \
        : "r"(a[0]), "r"(a[1]), "r"(a[2]), "r"(a[3]), "r"(b[0]), "r"(b[1]))

#define MMA_F16(d, a, b) \
    asm volatile("mma.sync.aligned.m16n8k16.row.col.f32.f16.f16.f32 " \
        "{%0,%1,%2,%3}, {%4,%5,%6,%7}, {%8,%9}, {%0,%1,%2,%3};" \
        : "+f"(d[0]), "+f"(d[1]), "+f"(d[2]), "+f"(d[3]) \
        : "r"(a[0]), "r"(a[1]), "r"(a[2]), "r"(a[3]), "r"(b[0]), "r"(b[1]))

// ------------------------- fp32 -> fp16 convert --------------------------------
__global__ __launch_bounds__(256) void tofp16(
    const float* __restrict__ src, __half* __restrict__ dst)
{
    size_t i = ((size_t)blockIdx.x * 256 + threadIdx.x) * 4;
    float4 v = *reinterpret_cast<const float4*>(src + i);
    __half2* pd = reinterpret_cast<__half2*>(dst + i);
    pd[0] = __floats2half2_rn(v.x, v.y);
    pd[1] = __floats2half2_rn(v.z, v.w);
}

// ------------------------- fp32 -> bf16 hi/lo split ---------------------------
__global__ __launch_bounds__(256) void split32(
    const float* __restrict__ src,
    __nv_bfloat16* __restrict__ hi, __nv_bfloat16* __restrict__ lo)
{
    size_t i = ((size_t)blockIdx.x * 256 + threadIdx.x) * 4;
    float4 v = *reinterpret_cast<const float4*>(src + i);
    float vv[4] = {v.x, v.y, v.z, v.w};
    __nv_bfloat16 h[4], l[4];
#pragma unroll
    for (int c = 0; c < 4; c++) {
        h[c] = __float2bfloat16(vv[c]);
        l[c] = __float2bfloat16(vv[c] - __bfloat162float(h[c]));
    }
    __nv_bfloat162* ph = reinterpret_cast<__nv_bfloat162*>(hi + i);
    __nv_bfloat162* pl = reinterpret_cast<__nv_bfloat162*>(lo + i);
    ph[0] = __nv_bfloat162(h[0], h[1]);
    ph[1] = __nv_bfloat162(h[2], h[3]);
    pl[0] = __nv_bfloat162(l[0], l[1]);
    pl[1] = __nv_bfloat162(l[2], l[3]);
}

// -------------------- single-pass fp16 GEMM (dual output) ---------------------
// C[m][n] = sum_k A[m][k]*B[n][k]; gridDim.x=16: bx<8 -> (B1,C1), else (B2,C2).
// 128x128 tile, BK=64, 3-stage cp.async, ldmatrix.x4, XOR swizzle.

#define PART_B 16384               // 128 rows x 128B (64 halves)
#define STAGE_F16 (2*PART_B)       // A|B = 32KB per stage
#define NSTAGE 3
#define DYN_F16 (NSTAGE*STAGE_F16 + 1024)

__global__ __launch_bounds__(256, 1) void gemm_f16(
    const __half* __restrict__ A,
    const __half* __restrict__ B1, const __half* __restrict__ B2,
    float* __restrict__ C1, float* __restrict__ C2,
    int M, int N, int K)
{
    extern __shared__ char dyn[];
    const uint32_t tile = (s2u(dyn) + 127u) & ~127u;

    const int tid = threadIdx.x;
    const int bx = blockIdx.x;
    const bool first = bx < 8;
    const __half* B = first ? B1 : B2;
    float* C = first ? C1 : C2;
    const int m0 = blockIdx.y * 128;
    const int n0 = (bx & 7) * 128;

    const int wid = tid >> 5, lane = tid & 31;
    const int wm = wid >> 2;       // 0..1
    const int wn = wid & 3;        // 0..3

    const __half* srcs[2] = { A + (size_t)m0 * K, B + (size_t)n0 * K };

    const int lr = tid >> 1;
    const int lc0 = (tid & 1) * 4;
    const int lsw = lr & 7;

    auto issue = [&](int s) {
        uint32_t sb = tile + (uint32_t)(s % NSTAGE) * STAGE_F16;
        int k0 = s * 64;
#pragma unroll
        for (int p = 0; p < 2; p++) {
            const __half* g = srcs[p] + (size_t)lr * K + k0 + lc0 * 8;
            uint32_t base = sb + p * PART_B + lr * 128;
#pragma unroll
            for (int c = 0; c < 4; c++)
                cp16(base + (((lc0 + c) ^ lsw) << 4), g + c * 8);
        }
        CP_COMMIT();
    };

    const int arow = wm * 64 + (lane & 15);
    const int ahalf = lane >> 4;
    const int asw = arow & 7;
    const int brow = wn * 32 + ((lane >> 4) << 3) + (lane & 7);
    const int bhalf = (lane >> 3) & 1;
    const int bsw = brow & 7;

    float acc[4][4][4];
#pragma unroll
    for (int i = 0; i < 4; i++)
#pragma unroll
        for (int j = 0; j < 4; j++)
#pragma unroll
            for (int c = 0; c < 4; c++) acc[i][j][c] = 0.f;

    issue(0); issue(1);

    const int NIT = K / 64;
    for (int it = 0; it < NIT; ++it) {
        if (it + 1 < NIT) asm volatile("cp.async.wait_group 1;" ::: "memory");
        else              asm volatile("cp.async.wait_group 0;" ::: "memory");
        __syncthreads();
        if (it + 2 < NIT) issue(it + 2);

        uint32_t sb = tile + (uint32_t)(it % NSTAGE) * STAGE_F16;
        uint32_t aA = sb          + arow * 128;
        uint32_t aB = sb + PART_B + brow * 128;

#pragma unroll
        for (int ks = 0; ks < 4; ks++) {
            const int ac = (2 * ks + ahalf) ^ asw;
            const int bc = (2 * ks + bhalf) ^ bsw;
            uint32_t a[4][4], b[4][2];
#pragma unroll
            for (int i = 0; i < 4; i++)
                ldsm4(a[i], aA + i * (16 * 128) + (ac << 4));
#pragma unroll
            for (int q = 0; q < 2; q++) {
                uint32_t rb[4];
                ldsm4(rb, aB + q * (16 * 128) + (bc << 4));
                b[q*2+0][0] = rb[0]; b[q*2+0][1] = rb[1];
                b[q*2+1][0] = rb[2]; b[q*2+1][1] = rb[3];
            }
#pragma unroll
            for (int i = 0; i < 4; i++)
#pragma unroll
                for (int j = 0; j < 4; j++)
                    MMA_F16(acc[i][j], a[i], b[j]);
        }
    }

    const int g = lane >> 2, tq = lane & 3;
#pragma unroll
    for (int i = 0; i < 4; i++) {
        const int m = m0 + wm * 64 + i * 16 + g;
#pragma unroll
        for (int j = 0; j < 4; j++) {
            const int n = n0 + wn * 32 + j * 8 + tq * 2;
            float2 v0 = { acc[i][j][0], acc[i][j][1] };
            float2 v1 = { acc[i][j][2], acc[i][j][3] };
            *reinterpret_cast<float2*>(C + (size_t)m * N + n)       = v0;
            *reinterpret_cast<float2*>(C + (size_t)(m + 8) * N + n) = v1;
        }
    }
}

// ---------------------- bf16-split 3-pass GEMM (output) -----------------------
#define STAGE_B (4*PART_B)         // Ahi|Alo|Bhi|Blo = 64KB per stage
#define DYN_B (NSTAGE*STAGE_B + 1024)

__global__ __launch_bounds__(256, 1) void gemm_bf16x2(
    const __nv_bfloat16* __restrict__ Ahi, const __nv_bfloat16* __restrict__ Alo,
    const __nv_bfloat16* __restrict__ Bhi, const __nv_bfloat16* __restrict__ Blo,
    const float* __restrict__ bias, float* __restrict__ C,
    int M, int N, int K)
{
    extern __shared__ char dyn[];
    const uint32_t tile = (s2u(dyn) + 127u) & ~127u;

    const int tid = threadIdx.x;
    const int m0 = blockIdx.y * 128;
    const int n0 = blockIdx.x * 128;

    const int wid = tid >> 5, lane = tid & 31;
    const int wm = wid >> 2;
    const int wn = wid & 3;

    const __nv_bfloat16* srcs[4] = {
        Ahi + (size_t)m0 * K, Alo + (size_t)m0 * K,
        Bhi + (size_t)n0 * K, Blo + (size_t)n0 * K };

    const int lr = tid >> 1;
    const int lc0 = (tid & 1) * 4;
    const int lsw = lr & 7;

    auto issue = [&](int s) {
        uint32_t sb = tile + (uint32_t)(s % NSTAGE) * STAGE_B;
        int k0 = s * 64;
#pragma unroll
        for (int p = 0; p < 4; p++) {
            const __nv_bfloat16* g = srcs[p] + (size_t)lr * K + k0 + lc0 * 8;
            uint32_t base = sb + p * PART_B + lr * 128;
#pragma unroll
            for (int c = 0; c < 4; c++)
                cp16(base + (((lc0 + c) ^ lsw) << 4), g + c * 8);
        }
        CP_COMMIT();
    };

    const int arow = wm * 64 + (lane & 15);
    const int ahalf = lane >> 4;
    const int asw = arow & 7;
    const int brow = wn * 32 + ((lane >> 4) << 3) + (lane & 7);
    const int bhalf = (lane >> 3) & 1;
    const int bsw = brow & 7;

    float acc[4][4][4];
#pragma unroll
    for (int i = 0; i < 4; i++)
#pragma unroll
        for (int j = 0; j < 4; j++)
#pragma unroll
            for (int c = 0; c < 4; c++) acc[i][j][c] = 0.f;

    issue(0); issue(1);

    const int NIT = K / 64;
    for (int it = 0; it < NIT; ++it) {
        if (it + 1 < NIT) asm volatile("cp.async.wait_group 1;" ::: "memory");
        else              asm volatile("cp.async.wait_group 0;" ::: "memory");
        __syncthreads();
        if (it + 2 < NIT) issue(it + 2);

        uint32_t sb = tile + (uint32_t)(it % NSTAGE) * STAGE_B;
        uint32_t aAhi = sb              + arow * 128;
        uint32_t aAlo = sb +     PART_B + arow * 128;
        uint32_t aBhi = sb + 2 * PART_B + brow * 128;
        uint32_t aBlo = sb + 3 * PART_B + brow * 128;

#pragma unroll
        for (int ks = 0; ks < 4; ks++) {
            const int ac = (2 * ks + ahalf) ^ asw;
            const int bc = (2 * ks + bhalf) ^ bsw;
            uint32_t ahi[4][4], alo[4][4], bhi[4][2], blo[4][2];
#pragma unroll
            for (int i = 0; i < 4; i++) {
                ldsm4(ahi[i], aAhi + i * (16 * 128) + (ac << 4));
                ldsm4(alo[i], aAlo + i * (16 * 128) + (ac << 4));
            }
#pragma unroll
            for (int q = 0; q < 2; q++) {
                uint32_t rb[4];
                ldsm4(rb, aBhi + q * (16 * 128) + (bc << 4));
                bhi[q*2+0][0] = rb[0]; bhi[q*2+0][1] = rb[1];
                bhi[q*2+1][0] = rb[2]; bhi[q*2+1][1] = rb[3];
                ldsm4(rb, aBlo + q * (16 * 128) + (bc << 4));
                blo[q*2+0][0] = rb[0]; blo[q*2+0][1] = rb[1];
                blo[q*2+1][0] = rb[2]; blo[q*2+1][1] = rb[3];
            }
#pragma unroll
            for (int i = 0; i < 4; i++)
#pragma unroll
                for (int j = 0; j < 4; j++) {
                    MMA_BF16(acc[i][j], ahi[i], bhi[j]);
                    MMA_BF16(acc[i][j], ahi[i], blo[j]);
                    MMA_BF16(acc[i][j], alo[i], bhi[j]);
                }
        }
    }

    const int g = lane >> 2, tq = lane & 3;
#pragma unroll
    for (int i = 0; i < 4; i++) {
        const int m = m0 + wm * 64 + i * 16 + g;
#pragma unroll
        for (int j = 0; j < 4; j++) {
            const int n = n0 + wn * 32 + j * 8 + tq * 2;
            float b0 = bias[n], b1 = bias[n + 1];
            float2 v0 = { acc[i][j][0] + b0, acc[i][j][1] + b1 };
            float2 v1 = { acc[i][j][2] + b0, acc[i][j][3] + b1 };
            *reinterpret_cast<float2*>(C + (size_t)m * N + n)       = v0;
            *reinterpret_cast<float2*>(C + (size_t)(m + 8) * N + n) = v1;
        }
    }
}

// ---- pass A (fused): gate/alpha/beta from raw GEMM outputs + local scan ------
__global__ __launch_bounds__(256) void scan_local(
    float* __restrict__ ih_arr, float* __restrict__ gate_arr,
    const float* __restrict__ b_ih, const float* __restrict__ b_g,
    const float* __restrict__ log_a,
    float* __restrict__ cA, float* __restrict__ cB)
{
    int idx = blockIdx.x * blockDim.x + threadIdx.x;
    int h = idx % CH;
    int c = (idx / CH) % NCHUNK;
    int b = idx / (CH * NCHUNK);
    const float bg = b_g[h], bi = b_ih[h], ea = __expf(log_a[h]);
    size_t base = ((size_t)b * CT + (size_t)c * CHUNK) * CH + h;
    float p = 1.f, hl = 0.f;
#pragma unroll 8
    for (int t = 0; t < CHUNK; t++) {
        size_t o = base + (size_t)t * CH;
        float graw = gate_arr[o];
        float iraw = ih_arr[o];
        float gate = 1.f / (1.f + __expf(-(graw + bg)));
        float beta = gate * (iraw + bi);
        float a = (1.f - gate) * ea;
        hl = fmaf(a, hl, beta);
        p *= a;
        gate_arr[o] = p;
        ih_arr[o] = hl;
    }
    cA[((size_t)b * NCHUNK + c) * CH + h] = p;
    cB[((size_t)b * NCHUNK + c) * CH + h] = hl;
}

// ---------------- pass B: scan across chunk summaries per (b,h) ---------------
__global__ __launch_bounds__(256) void scan_carry(
    const float* __restrict__ cA, const float* __restrict__ cB,
    float* __restrict__ pref)
{
    int idx = blockIdx.x * blockDim.x + threadIdx.x;
    int h = idx % CH;
    int b = idx / CH;
    float run = 0.f;
#pragma unroll
    for (int c = 0; c < NCHUNK; c++) {
        size_t o = ((size_t)b * NCHUNK + c) * CH + h;
        pref[o] = run;
        run = fmaf(cA[o], run, cB[o]);
    }
}

// ------- pass C: fixup h = h_local + P*carry, fused LayerNorm -> bf16 hi/lo ----
__global__ __launch_bounds__(256) void fix_ln(
    const float* __restrict__ P, const float* __restrict__ HL,
    const float* __restrict__ pref,
    const float* __restrict__ lng, const float* __restrict__ lnb,
    __nv_bfloat16* __restrict__ hnhi, __nv_bfloat16* __restrict__ hnlo)
{
    __shared__ float sred[16];
    const int row = blockIdx.x;
    const int b = row / CT;
    const int t = row % CT;
    const int c = t / CHUNK;
    const size_t base = (size_t)row * CH;
    const float* prow = pref + ((size_t)b * NCHUNK + c) * CH;
    const int h = threadIdx.x * 4;

    float4 p4  = *reinterpret_cast<const float4*>(P + base + h);
    float4 hl4 = *reinterpret_cast<const float4*>(HL + base + h);
    float4 pr4 = *reinterpret_cast<const float4*>(prow + h);
    float v[4];
    v[0] = fmaf(p4.x, pr4.x, hl4.x);
    v[1] = fmaf(p4.y, pr4.y, hl4.y);
    v[2] = fmaf(p4.z, pr4.z, hl4.z);
    v[3] = fmaf(p4.w, pr4.w, hl4.w);

    float s = v[0] + v[1] + v[2] + v[3];
    float ss = v[0]*v[0] + v[1]*v[1] + v[2]*v[2] + v[3]*v[3];
#pragma unroll
    for (int off = 16; off > 0; off >>= 1) {
        s  += __shfl_xor_sync(0xffffffffu, s,  off);
        ss += __shfl_xor_sync(0xffffffffu, ss, off);
    }
    const int warp = threadIdx.x >> 5, lane = threadIdx.x & 31;
    if (lane == 0) { sred[warp] = s; sred[8 + warp] = ss; }
    __syncthreads();
    if (threadIdx.x < 32) {
        float a  = (lane < 8) ? sred[lane]     : 0.f;
        float b2 = (lane < 8) ? sred[8 + lane] : 0.f;
#pragma unroll
        for (int off = 4; off > 0; off >>= 1) {
            a  += __shfl_xor_sync(0xffffffffu, a,  off);
            b2 += __shfl_xor_sync(0xffffffffu, b2, off);
        }
        if (lane == 0) { sred[0] = a; sred[1] = b2; }
    }
    __syncthreads();
    const float mu  = sred[0] * (1.f / CH);
    const float var = sred[1] * (1.f / CH) - mu * mu;
    const float inv = rsqrtf(var + LN_EPS);

    float4 g4 = *reinterpret_cast<const float4*>(lng + h);
    float4 b4 = *reinterpret_cast<const float4*>(lnb + h);
    float o[4];
    o[0] = (v[0] - mu) * inv * g4.x + b4.x;
    o[1] = (v[1] - mu) * inv * g4.y + b4.y;
    o[2] = (v[2] - mu) * inv * g4.z + b4.z;
    o[3] = (v[3] - mu) * inv * g4.w + b4.w;

    __nv_bfloat16 hi[4], lo[4];
#pragma unroll
    for (int k = 0; k < 4; k++) {
        hi[k] = __float2bfloat16(o[k]);
        lo[k] = __float2bfloat16(o[k] - __bfloat162float(hi[k]));
    }
    __nv_bfloat162* phh = reinterpret_cast<__nv_bfloat162*>(hnhi + base + h);
    __nv_bfloat162* pll = reinterpret_cast<__nv_bfloat162*>(hnlo + base + h);
    phh[0] = __nv_bfloat162(hi[0], hi[1]);
    phh[1] = __nv_bfloat162(hi[2], hi[3]);
    pll[0] = __nv_bfloat162(lo[0], lo[1]);
    pll[1] = __nv_bfloat162(lo[2], lo[3]);
}

// --------------------------------- launcher ----------------------------------
extern "C" void kernel_launch(void* const* d_in, const int* in_sizes, int n_in,
                              void* d_out, int out_size)
{
    const float* x      = (const float*)d_in[0];
    const float* W_ih   = (const float*)d_in[1];
    const float* b_ih   = (const float*)d_in[2];
    const float* log_a  = (const float*)d_in[3];
    const float* W_gate = (const float*)d_in[4];
    const float* b_gate = (const float*)d_in[5];
    const float* W_out  = (const float*)d_in[6];
    const float* b_out  = (const float*)d_in[7];
    const float* ln_g   = (const float*)d_in[8];
    const float* ln_b   = (const float*)d_in[9];
    float* out = (float*)d_out;

    __half *xh, *w1h, *w2h;
    __nv_bfloat16 *w3hi, *w3lo, *hnhi, *hnlo;
    float *ih, *gt, *cA, *cB, *pref;
    cudaGetSymbolAddress((void**)&xh,   g_xh);
    cudaGetSymbolAddress((void**)&w1h,  g_w1h);
    cudaGetSymbolAddress((void**)&w2h,  g_w2h);
    cudaGetSymbolAddress((void**)&w3hi, g_w3hi);
    cudaGetSymbolAddress((void**)&w3lo, g_w3lo);
    cudaGetSymbolAddress((void**)&hnhi, g_hnhi);
    cudaGetSymbolAddress((void**)&hnlo, g_hnlo);
    cudaGetSymbolAddress((void**)&ih,   g_ih);
    cudaGetSymbolAddress((void**)&gt,   g_gate);
    cudaGetSymbolAddress((void**)&cA,   g_cA);
    cudaGetSymbolAddress((void**)&cB,   g_cB);
    cudaGetSymbolAddress((void**)&pref, g_pref);

    cudaFuncSetAttribute(gemm_f16,
                         cudaFuncAttributeMaxDynamicSharedMemorySize, DYN_F16);
    cudaFuncSetAttribute(gemm_bf16x2,
                         cudaFuncAttributeMaxDynamicSharedMemorySize, DYN_B);

    // conversions
    tofp16<<<(size_t)CM * CD / 4 / 256, 256>>>(x,      xh);
    tofp16<<<(size_t)CH * CD / 4 / 256, 256>>>(W_ih,   w1h);
    tofp16<<<(size_t)CH * CD / 4 / 256, 256>>>(W_gate, w2h);
    split32<<<(size_t)CO * CH / 4 / 256, 256>>>(W_out, w3hi, w3lo);

    // fused dual input GEMM (fp16, single pass): bx<8 -> ih, bx>=8 -> gate
    gemm_f16<<<dim3(16, CM / 128), 256, DYN_F16>>>(
        xh, w1h, w2h, ih, gt, CM, CH, CD);

    // fused elementwise + chunked scan
    scan_local<<<(CB * CH * NCHUNK) / 256, 256>>>(ih, gt, b_ih, b_gate, log_a, cA, cB);
    scan_carry<<<(CB * CH) / 256, 256>>>(cA, cB, pref);
    fix_ln<<<CM, 256>>>(gt, ih, pref, ln_g, ln_b, hnhi, hnlo);

    // output GEMM (bf16 3-pass, high precision)
    gemm_bf16x2<<<dim3(CO / 128, CM / 128), 256, DYN_B>>>(
        hnhi, hnlo, w3hi, w3lo, b_out, out, CM, CO, CH);
}

// round 8
// speedup vs baseline: 3.7952x; 1.1404x over previous
#include <cuda_runtime.h>
#include <cuda_bf16.h>
#include <cuda_fp16.h>
#include <cstdint>

// Problem constants (fixed shapes from reference)
#define CB 4
#define CT 8192
#define CD 1024
#define CH 1024
#define CO 1024
#define CM (CB*CT)    // 32768 rows
#define NCHUNK 64
#define CHUNK (CT/NCHUNK)   // 128
#define LN_EPS 1e-5f
#define LOSCALE 2048.0f

// ---------------- scratch (device globals; no allocation allowed) -------------
__device__ __half g_xh[(size_t)CM*CD];
__device__ __half g_w1h[(size_t)CH*CD], g_w2h[(size_t)CH*CD];
__device__ __half g_w3hi[(size_t)CO*CH], g_w3lo[(size_t)CO*CH];
__device__ __half g_hnh[(size_t)CM*CH];
__device__ float g_ih[(size_t)CM*CH];
__device__ float g_gate[(size_t)CM*CH];
__device__ float g_cA[CB*NCHUNK*CH];
__device__ float g_cB[CB*NCHUNK*CH];
__device__ float g_pref[CB*NCHUNK*CH];

// ------------------------------ helpers ---------------------------------------
__device__ __forceinline__ uint32_t s2u(const void* p) {
    return (uint32_t)__cvta_generic_to_shared(p);
}
__device__ __forceinline__ void cp16(uint32_t s, const void* g) {
    asm volatile("cp.async.cg.shared.global [%0], [%1], 16;" :: "r"(s), "l"(g));
}
#define CP_COMMIT() asm volatile("cp.async.commit_group;" ::: "memory")

__device__ __forceinline__ void ldsm4(uint32_t* r, uint32_t addr) {
    asm volatile("ldmatrix.sync.aligned.m8n8.x4.shared.b16 {%0,%1,%2,%3}, [%4];"
        : "=r"(r[0]), "=r"(r[1]), "=r"(r[2]), "=r"(r[3]) : "r"(addr));
}

#define MMA_F16(d, a, b) \
    asm volatile("mma.sync.aligned.m16n8k16.row.col.f32.f16.f16.f32 " \
        "{%0,%1,%2,%3}, {%4,%5,%6,%7}, {%8,%9}, {%0,%1,%2,%3};" \
        : "+f"(d[0]), "+f"(d[1]), "+f"(d[2]), "+f"(d[3]) \
        : "r"(a[0]), "r"(a[1]), "r"(a[2]), "r"(a[3]), "r"(b[0]), "r"(b[1]))

// ------------------------- fp32 -> fp16 convert --------------------------------
__global__ __launch_bounds__(256) void tofp16(
    const float* __restrict__ src, __half* __restrict__ dst)
{
    size_t i = ((size_t)blockIdx.x * 256 + threadIdx.x) * 4;
    float4 v = *reinterpret_cast<const float4*>(src + i);
    __half2* pd = reinterpret_cast<__half2*>(dst + i);
    pd[0] = __floats2half2_rn(v.x, v.y);
    pd[1] = __floats2half2_rn(v.z, v.w);
}

// -------------------- fp32 -> fp16 hi + scaled-lo split -----------------------
__global__ __launch_bounds__(256) void splitf16(
    const float* __restrict__ src,
    __half* __restrict__ hi, __half* __restrict__ lo)
{
    size_t i = ((size_t)blockIdx.x * 256 + threadIdx.x) * 4;
    float4 v = *reinterpret_cast<const float4*>(src + i);
    float vv[4] = {v.x, v.y, v.z, v.w};
    __half h[4], l[4];
#pragma unroll
    for (int c = 0; c < 4; c++) {
        h[c] = __float2half_rn(vv[c]);
        l[c] = __float2half_rn((vv[c] - __half2float(h[c])) * LOSCALE);
    }
    __half2* ph = reinterpret_cast<__half2*>(hi + i);
    __half2* pl = reinterpret_cast<__half2*>(lo + i);
    ph[0] = __halves2half2(h[0], h[1]);
    ph[1] = __halves2half2(h[2], h[3]);
    pl[0] = __halves2half2(l[0], l[1]);
    pl[1] = __halves2half2(l[2], l[3]);
}

// -------------------- single-pass fp16 GEMM (dual output) ---------------------
// C[m][n] = sum_k A[m][k]*B[n][k]; gridDim.x=16: bx<8 -> (B1,C1), else (B2,C2).
// 128x128 tile, BK=64, 3-stage cp.async, ldmatrix.x4, XOR swizzle.

#define PART_B 16384               // 128 rows x 128B (64 halves)
#define STAGE_F16 (2*PART_B)       // A|B = 32KB per stage
#define NSTAGE 3
#define DYN_F16 (NSTAGE*STAGE_F16 + 1024)

__global__ __launch_bounds__(256, 1) void gemm_f16(
    const __half* __restrict__ A,
    const __half* __restrict__ B1, const __half* __restrict__ B2,
    float* __restrict__ C1, float* __restrict__ C2,
    int M, int N, int K)
{
    extern __shared__ char dyn[];
    const uint32_t tile = (s2u(dyn) + 127u) & ~127u;

    const int tid = threadIdx.x;
    const int bx = blockIdx.x;
    const bool first = bx < 8;
    const __half* B = first ? B1 : B2;
    float* C = first ? C1 : C2;
    const int m0 = blockIdx.y * 128;
    const int n0 = (bx & 7) * 128;

    const int wid = tid >> 5, lane = tid & 31;
    const int wm = wid >> 2;
    const int wn = wid & 3;

    const __half* srcs[2] = { A + (size_t)m0 * K, B + (size_t)n0 * K };

    const int lr = tid >> 1;
    const int lc0 = (tid & 1) * 4;
    const int lsw = lr & 7;

    auto issue = [&](int s) {
        uint32_t sb = tile + (uint32_t)(s % NSTAGE) * STAGE_F16;
        int k0 = s * 64;
#pragma unroll
        for (int p = 0; p < 2; p++) {
            const __half* g = srcs[p] + (size_t)lr * K + k0 + lc0 * 8;
            uint32_t base = sb + p * PART_B + lr * 128;
#pragma unroll
            for (int c = 0; c < 4; c++)
                cp16(base + (((lc0 + c) ^ lsw) << 4), g + c * 8);
        }
        CP_COMMIT();
    };

    const int arow = wm * 64 + (lane & 15);
    const int ahalf = lane >> 4;
    const int asw = arow & 7;
    const int brow = wn * 32 + ((lane >> 4) << 3) + (lane & 7);
    const int bhalf = (lane >> 3) & 1;
    const int bsw = brow & 7;

    float acc[4][4][4];
#pragma unroll
    for (int i = 0; i < 4; i++)
#pragma unroll
        for (int j = 0; j < 4; j++)
#pragma unroll
            for (int c = 0; c < 4; c++) acc[i][j][c] = 0.f;

    issue(0); issue(1);

    const int NIT = K / 64;
    for (int it = 0; it < NIT; ++it) {
        if (it + 1 < NIT) asm volatile("cp.async.wait_group 1;" ::: "memory");
        else              asm volatile("cp.async.wait_group 0;" ::: "memory");
        __syncthreads();
        if (it + 2 < NIT) issue(it + 2);

        uint32_t sb = tile + (uint32_t)(it % NSTAGE) * STAGE_F16;
        uint32_t aA = sb          + arow * 128;
        uint32_t aB = sb + PART_B + brow * 128;

#pragma unroll
        for (int ks = 0; ks < 4; ks++) {
            const int ac = (2 * ks + ahalf) ^ asw;
            const int bc = (2 * ks + bhalf) ^ bsw;
            uint32_t a[4][4], b[4][2];
#pragma unroll
            for (int i = 0; i < 4; i++)
                ldsm4(a[i], aA + i * (16 * 128) + (ac << 4));
#pragma unroll
            for (int q = 0; q < 2; q++) {
                uint32_t rb[4];
                ldsm4(rb, aB + q * (16 * 128) + (bc << 4));
                b[q*2+0][0] = rb[0]; b[q*2+0][1] = rb[1];
                b[q*2+1][0] = rb[2]; b[q*2+1][1] = rb[3];
            }
#pragma unroll
            for (int i = 0; i < 4; i++)
#pragma unroll
                for (int j = 0; j < 4; j++)
                    MMA_F16(acc[i][j], a[i], b[j]);
        }
    }

    const int g = lane >> 2, tq = lane & 3;
#pragma unroll
    for (int i = 0; i < 4; i++) {
        const int m = m0 + wm * 64 + i * 16 + g;
#pragma unroll
        for (int j = 0; j < 4; j++) {
            const int n = n0 + wn * 32 + j * 8 + tq * 2;
            float2 v0 = { acc[i][j][0], acc[i][j][1] };
            float2 v1 = { acc[i][j][2], acc[i][j][3] };
            *reinterpret_cast<float2*>(C + (size_t)m * N + n)       = v0;
            *reinterpret_cast<float2*>(C + (size_t)(m + 8) * N + n) = v1;
        }
    }
}

// ------------- fp16 2-pass GEMM (A exactish via B hi/lo split) -----------------
// C = A*Bhi_acc + (A*Blo_acc)/LOSCALE + bias. A: hn fp16; B: W_out hi/lo fp16.
#define STAGE_F16X2 (3*PART_B)     // A|Bhi|Blo = 48KB per stage
#define DYN_F16X2 (NSTAGE*STAGE_F16X2 + 1024)

__global__ __launch_bounds__(256, 1) void gemm_f16x2(
    const __half* __restrict__ A,
    const __half* __restrict__ Bhi, const __half* __restrict__ Blo,
    const float* __restrict__ bias, float* __restrict__ C,
    int M, int N, int K)
{
    extern __shared__ char dyn[];
    const uint32_t tile = (s2u(dyn) + 127u) & ~127u;

    const int tid = threadIdx.x;
    const int m0 = blockIdx.y * 128;
    const int n0 = blockIdx.x * 128;

    const int wid = tid >> 5, lane = tid & 31;
    const int wm = wid >> 2;
    const int wn = wid & 3;

    const __half* srcs[3] = {
        A + (size_t)m0 * K, Bhi + (size_t)n0 * K, Blo + (size_t)n0 * K };

    const int lr = tid >> 1;
    const int lc0 = (tid & 1) * 4;
    const int lsw = lr & 7;

    auto issue = [&](int s) {
        uint32_t sb = tile + (uint32_t)(s % NSTAGE) * STAGE_F16X2;
        int k0 = s * 64;
#pragma unroll
        for (int p = 0; p < 3; p++) {
            const __half* g = srcs[p] + (size_t)lr * K + k0 + lc0 * 8;
            uint32_t base = sb + p * PART_B + lr * 128;
#pragma unroll
            for (int c = 0; c < 4; c++)
                cp16(base + (((lc0 + c) ^ lsw) << 4), g + c * 8);
        }
        CP_COMMIT();
    };

    const int arow = wm * 64 + (lane & 15);
    const int ahalf = lane >> 4;
    const int asw = arow & 7;
    const int brow = wn * 32 + ((lane >> 4) << 3) + (lane & 7);
    const int bhalf = (lane >> 3) & 1;
    const int bsw = brow & 7;

    float acch[4][4][4], accl[4][4][4];
#pragma unroll
    for (int i = 0; i < 4; i++)
#pragma unroll
        for (int j = 0; j < 4; j++)
#pragma unroll
            for (int c = 0; c < 4; c++) { acch[i][j][c] = 0.f; accl[i][j][c] = 0.f; }

    issue(0); issue(1);

    const int NIT = K / 64;
    for (int it = 0; it < NIT; ++it) {
        if (it + 1 < NIT) asm volatile("cp.async.wait_group 1;" ::: "memory");
        else              asm volatile("cp.async.wait_group 0;" ::: "memory");
        __syncthreads();
        if (it + 2 < NIT) issue(it + 2);

        uint32_t sb = tile + (uint32_t)(it % NSTAGE) * STAGE_F16X2;
        uint32_t aA  = sb              + arow * 128;
        uint32_t aBh = sb +     PART_B + brow * 128;
        uint32_t aBl = sb + 2 * PART_B + brow * 128;

#pragma unroll
        for (int ks = 0; ks < 4; ks++) {
            const int ac = (2 * ks + ahalf) ^ asw;
            const int bc = (2 * ks + bhalf) ^ bsw;
            uint32_t a[4][4], bh[4][2], bl[4][2];
#pragma unroll
            for (int i = 0; i < 4; i++)
                ldsm4(a[i], aA + i * (16 * 128) + (ac << 4));
#pragma unroll
            for (int q = 0; q < 2; q++) {
                uint32_t rb[4];
                ldsm4(rb, aBh + q * (16 * 128) + (bc << 4));
                bh[q*2+0][0] = rb[0]; bh[q*2+0][1] = rb[1];
                bh[q*2+1][0] = rb[2]; bh[q*2+1][1] = rb[3];
                ldsm4(rb, aBl + q * (16 * 128) + (bc << 4));
                bl[q*2+0][0] = rb[0]; bl[q*2+0][1] = rb[1];
                bl[q*2+1][0] = rb[2]; bl[q*2+1][1] = rb[3];
            }
#pragma unroll
            for (int i = 0; i < 4; i++)
#pragma unroll
                for (int j = 0; j < 4; j++) {
                    MMA_F16(acch[i][j], a[i], bh[j]);
                    MMA_F16(accl[i][j], a[i], bl[j]);
                }
        }
    }

    const float inv = 1.0f / LOSCALE;
    const int g = lane >> 2, tq = lane & 3;
#pragma unroll
    for (int i = 0; i < 4; i++) {
        const int m = m0 + wm * 64 + i * 16 + g;
#pragma unroll
        for (int j = 0; j < 4; j++) {
            const int n = n0 + wn * 32 + j * 8 + tq * 2;
            float b0 = bias[n], b1 = bias[n + 1];
            float2 v0, v1;
            v0.x = fmaf(accl[i][j][0], inv, acch[i][j][0]) + b0;
            v0.y = fmaf(accl[i][j][1], inv, acch[i][j][1]) + b1;
            v1.x = fmaf(accl[i][j][2], inv, acch[i][j][2]) + b0;
            v1.y = fmaf(accl[i][j][3], inv, acch[i][j][3]) + b1;
            *reinterpret_cast<float2*>(C + (size_t)m * N + n)       = v0;
            *reinterpret_cast<float2*>(C + (size_t)(m + 8) * N + n) = v1;
        }
    }
}

// ---- pass A (fused): gate/alpha/beta from raw GEMM outputs + local scan ------
__global__ __launch_bounds__(256) void scan_local(
    float* __restrict__ ih_arr, float* __restrict__ gate_arr,
    const float* __restrict__ b_ih, const float* __restrict__ b_g,
    const float* __restrict__ log_a,
    float* __restrict__ cA, float* __restrict__ cB)
{
    int idx = blockIdx.x * blockDim.x + threadIdx.x;
    int h = idx % CH;
    int c = (idx / CH) % NCHUNK;
    int b = idx / (CH * NCHUNK);
    const float bg = b_g[h], bi = b_ih[h], ea = __expf(log_a[h]);
    size_t base = ((size_t)b * CT + (size_t)c * CHUNK) * CH + h;
    float p = 1.f, hl = 0.f;
#pragma unroll 8
    for (int t = 0; t < CHUNK; t++) {
        size_t o = base + (size_t)t * CH;
        float graw = gate_arr[o];
        float iraw = ih_arr[o];
        float gate = 1.f / (1.f + __expf(-(graw + bg)));
        float beta = gate * (iraw + bi);
        float a = (1.f - gate) * ea;
        hl = fmaf(a, hl, beta);
        p *= a;
        gate_arr[o] = p;
        ih_arr[o] = hl;
    }
    cA[((size_t)b * NCHUNK + c) * CH + h] = p;
    cB[((size_t)b * NCHUNK + c) * CH + h] = hl;
}

// ---------------- pass B: scan across chunk summaries per (b,h) ---------------
__global__ __launch_bounds__(256) void scan_carry(
    const float* __restrict__ cA, const float* __restrict__ cB,
    float* __restrict__ pref)
{
    int idx = blockIdx.x * blockDim.x + threadIdx.x;
    int h = idx % CH;
    int b = idx / CH;
    float run = 0.f;
#pragma unroll
    for (int c = 0; c < NCHUNK; c++) {
        size_t o = ((size_t)b * NCHUNK + c) * CH + h;
        pref[o] = run;
        run = fmaf(cA[o], run, cB[o]);
    }
}

// ------- pass C: fixup h = h_local + P*carry, fused LayerNorm -> fp16 ----------
__global__ __launch_bounds__(256) void fix_ln(
    const float* __restrict__ P, const float* __restrict__ HL,
    const float* __restrict__ pref,
    const float* __restrict__ lng, const float* __restrict__ lnb,
    __half* __restrict__ hnh)
{
    __shared__ float sred[16];
    const int row = blockIdx.x;
    const int b = row / CT;
    const int t = row % CT;
    const int c = t / CHUNK;
    const size_t base = (size_t)row * CH;
    const float* prow = pref + ((size_t)b * NCHUNK + c) * CH;
    const int h = threadIdx.x * 4;

    float4 p4  = *reinterpret_cast<const float4*>(P + base + h);
    float4 hl4 = *reinterpret_cast<const float4*>(HL + base + h);
    float4 pr4 = *reinterpret_cast<const float4*>(prow + h);
    float v[4];
    v[0] = fmaf(p4.x, pr4.x, hl4.x);
    v[1] = fmaf(p4.y, pr4.y, hl4.y);
    v[2] = fmaf(p4.z, pr4.z, hl4.z);
    v[3] = fmaf(p4.w, pr4.w, hl4.w);

    float s = v[0] + v[1] + v[2] + v[3];
    float ss = v[0]*v[0] + v[1]*v[1] + v[2]*v[2] + v[3]*v[3];
#pragma unroll
    for (int off = 16; off > 0; off >>= 1) {
        s  += __shfl_xor_sync(0xffffffffu, s,  off);
        ss += __shfl_xor_sync(0xffffffffu, ss, off);
    }
    const int warp = threadIdx.x >> 5, lane = threadIdx.x & 31;
    if (lane == 0) { sred[warp] = s; sred[8 + warp] = ss; }
    __syncthreads();
    if (threadIdx.x < 32) {
        float a  = (lane < 8) ? sred[lane]     : 0.f;
        float b2 = (lane < 8) ? sred[8 + lane] : 0.f;
#pragma unroll
        for (int off = 4; off > 0; off >>= 1) {
            a  += __shfl_xor_sync(0xffffffffu, a,  off);
            b2 += __shfl_xor_sync(0xffffffffu, b2, off);
        }
        if (lane == 0) { sred[0] = a; sred[1] = b2; }
    }
    __syncthreads();
    const float mu  = sred[0] * (1.f / CH);
    const float var = sred[1] * (1.f / CH) - mu * mu;
    const float inv = rsqrtf(var + LN_EPS);

    float4 g4 = *reinterpret_cast<const float4*>(lng + h);
    float4 b4 = *reinterpret_cast<const float4*>(lnb + h);
    float o[4];
    o[0] = (v[0] - mu) * inv * g4.x + b4.x;
    o[1] = (v[1] - mu) * inv * g4.y + b4.y;
    o[2] = (v[2] - mu) * inv * g4.z + b4.z;
    o[3] = (v[3] - mu) * inv * g4.w + b4.w;

    __half2* ph = reinterpret_cast<__half2*>(hnh + base + h);
    ph[0] = __floats2half2_rn(o[0], o[1]);
    ph[1] = __floats2half2_rn(o[2], o[3]);
}

// --------------------------------- launcher ----------------------------------
extern "C" void kernel_launch(void* const* d_in, const int* in_sizes, int n_in,
                              void* d_out, int out_size)
{
    const float* x      = (const float*)d_in[0];
    const float* W_ih   = (const float*)d_in[1];
    const float* b_ih   = (const float*)d_in[2];
    const float* log_a  = (const float*)d_in[3];
    const float* W_gate = (const float*)d_in[4];
    const float* b_gate = (const float*)d_in[5];
    const float* W_out  = (const float*)d_in[6];
    const float* b_out  = (const float*)d_in[7];
    const float* ln_g   = (const float*)d_in[8];
    const float* ln_b   = (const float*)d_in[9];
    float* out = (float*)d_out;

    __half *xh, *w1h, *w2h, *w3hi, *w3lo, *hnh;
    float *ih, *gt, *cA, *cB, *pref;
    cudaGetSymbolAddress((void**)&xh,   g_xh);
    cudaGetSymbolAddress((void**)&w1h,  g_w1h);
    cudaGetSymbolAddress((void**)&w2h,  g_w2h);
    cudaGetSymbolAddress((void**)&w3hi, g_w3hi);
    cudaGetSymbolAddress((void**)&w3lo, g_w3lo);
    cudaGetSymbolAddress((void**)&hnh,  g_hnh);
    cudaGetSymbolAddress((void**)&ih,   g_ih);
    cudaGetSymbolAddress((void**)&gt,   g_gate);
    cudaGetSymbolAddress((void**)&cA,   g_cA);
    cudaGetSymbolAddress((void**)&cB,   g_cB);
    cudaGetSymbolAddress((void**)&pref, g_pref);

    cudaFuncSetAttribute(gemm_f16,
                         cudaFuncAttributeMaxDynamicSharedMemorySize, DYN_F16);
    cudaFuncSetAttribute(gemm_f16x2,
                         cudaFuncAttributeMaxDynamicSharedMemorySize, DYN_F16X2);

    // conversions
    tofp16<<<(size_t)CM * CD / 4 / 256, 256>>>(x,      xh);
    tofp16<<<(size_t)CH * CD / 4 / 256, 256>>>(W_ih,   w1h);
    tofp16<<<(size_t)CH * CD / 4 / 256, 256>>>(W_gate, w2h);
    splitf16<<<(size_t)CO * CH / 4 / 256, 256>>>(W_out, w3hi, w3lo);

    // fused dual input GEMM (fp16, single pass): bx<8 -> ih, bx>=8 -> gate
    gemm_f16<<<dim3(16, CM / 128), 256, DYN_F16>>>(
        xh, w1h, w2h, ih, gt, CM, CH, CD);

    // fused elementwise + chunked scan
    scan_local<<<(CB * CH * NCHUNK) / 256, 256>>>(ih, gt, b_ih, b_gate, log_a, cA, cB);
    scan_carry<<<(CB * CH) / 256, 256>>>(cA, cB, pref);
    fix_ln<<<CM, 256>>>(gt, ih, pref, ln_g, ln_b, hnh);

    // output GEMM (fp16 2-pass: hn single, W_out hi/lo)
    gemm_f16x2<<<dim3(CO / 128, CM / 128), 256, DYN_F16X2>>>(
        hnh, w3hi, w3lo, b_out, out, CM, CO, CH);
}